// round 1
// baseline (speedup 1.0000x reference)
#include <cuda_runtime.h>

#define NN 512
#define NC 16
#define NK 262144   // 2^18

// Scratch grids: C x N x N complex, ping-pong between FFT passes. 32 MB each.
__device__ __align__(16) float2 g_bufA[NC * NN * NN];
__device__ __align__(16) float2 g_bufB[NC * NN * NN];

// ---------------------------------------------------------------------------
// Kernel 1: zero gridA (must re-zero on every graph replay)
// ---------------------------------------------------------------------------
__global__ void __launch_bounds__(256) zero_kernel() {
    int i = blockIdx.x * blockDim.x + threadIdx.x;   // 0 .. 2M-1 float4's
    float4* p = reinterpret_cast<float4*>(g_bufA);
    p[i] = make_float4(0.f, 0.f, 0.f, 0.f);
}

// ---------------------------------------------------------------------------
// Kernel 2: scatter-add samples onto grid.
// x = (xr + i xi) * dcf, deposited at (iy, ix) = round((traj+0.5)*N) mod N.
// The input-side ifftshift is folded in as a (-1)^(iy+ix) sign on the weight.
// ---------------------------------------------------------------------------
__global__ void __launch_bounds__(256) scatter_kernel(
    const float* __restrict__ xr, const float* __restrict__ xi,
    const float* __restrict__ traj, const float* __restrict__ dcf)
{
    int gid = blockIdx.x * blockDim.x + threadIdx.x;   // 0 .. NK*NC-1
    int k = gid & (NK - 1);
    int c = gid >> 18;

    float ty = traj[2 * k + 0];
    float tx = traj[2 * k + 1];
    // matches jnp.round (round-half-to-even) exactly
    int iy = __float2int_rn((ty + 0.5f) * (float)NN) & (NN - 1);
    int ix = __float2int_rn((tx + 0.5f) * (float)NN) & (NN - 1);

    float w = dcf[k];
    if ((iy + ix) & 1) w = -w;

    float vr = xr[c * NK + k] * w;
    float vi = xi[c * NK + k] * w;

    float* cell = reinterpret_cast<float*>(&g_bufA[c * NN * NN + iy * NN + ix]);
    atomicAdd(cell,     vr);
    atomicAdd(cell + 1, vi);
}

// ---------------------------------------------------------------------------
// Kernel 3/4: 512-point radix-2 Stockham FFT (inverse sign e^{+i2pi...},
// unnormalized). 4 lines per block, 256 threads (64 threads / line, 4
// butterflies each / stage). COL=false: FFT along x (rows), gridA -> gridB.
// COL=true: FFT along y (cols), gridB -> gridA, with load/store order chosen
// for contiguous 32B global chunks.
// ---------------------------------------------------------------------------
#define LPAD 4   // smem row padding to avoid bank conflicts in the I/O phases

template<bool COL>
__global__ void __launch_bounds__(256) fft_kernel() {
    __shared__ float2 bufA[4][NN + LPAD];
    __shared__ float2 bufB[4][NN + LPAD];
    __shared__ float2 tw[NN / 2];

    const int tid  = threadIdx.x;           // 0..255
    const int coil = blockIdx.y;
    const int l0   = blockIdx.x * 4;

    const float2* __restrict__ src = (COL ? g_bufB : g_bufA) + coil * NN * NN;
    float2*       __restrict__ dst = (COL ? g_bufA : g_bufB) + coil * NN * NN;

    // twiddle table: w[p] = exp(+i * 2*pi * p / 512)
    {
        float ang = 6.283185307179586f * (float)tid / (float)NN;
        float sv, cv;
        sincosf(ang, &sv, &cv);
        tw[tid] = make_float2(cv, sv);
    }

    // load 4 lines x 512 elems
#pragma unroll
    for (int r = 0; r < 8; r++) {
        int u = tid + r * 256;
        int e, l;
        if (COL) { l = u & 3;        e = u >> 2; }
        else     { e = u & (NN - 1); l = u >> 9; }
        float2 v = COL ? src[e * NN + (l0 + l)] : src[(l0 + l) * NN + e];
        bufA[l][e] = v;
    }

    float2 (*cur)[NN + LPAD] = bufA;
    float2 (*nxt)[NN + LPAD] = bufB;
    const int line = tid >> 6;
    const int lt   = tid & 63;
    int s = 1;

#pragma unroll
    for (int st = 0; st < 9; st++) {
        __syncthreads();
#pragma unroll
        for (int r = 0; r < 4; r++) {
            int t = lt + (r << 6);         // butterfly id 0..255
            int q = t & (s - 1);
            int p = t >> st;
            int ib = q + s * p;
            float2 a = cur[line][ib];
            float2 b = cur[line][ib + 256];
            float2 w = tw[p << st];
            float2 sum = make_float2(a.x + b.x, a.y + b.y);
            float dx = a.x - b.x;
            float dy = a.y - b.y;
            float2 pr = make_float2(dx * w.x - dy * w.y,
                                    dx * w.y + dy * w.x);
            int ob = q + 2 * s * p;
            nxt[line][ob]     = sum;
            nxt[line][ob + s] = pr;
        }
        float2 (*tmp)[NN + LPAD] = cur; cur = nxt; nxt = tmp;
        s <<= 1;
    }
    __syncthreads();

    // store
#pragma unroll
    for (int r = 0; r < 8; r++) {
        int u = tid + r * 256;
        int e, l;
        if (COL) { l = u & 3;        e = u >> 2; }
        else     { e = u & (NN - 1); l = u >> 9; }
        float2 v = cur[l][e];
        if (COL) dst[e * NN + (l0 + l)] = v;
        else     dst[(l0 + l) * NN + e] = v;
    }
}

// ---------------------------------------------------------------------------
// Kernel 5: out = (-1)^(ny+nx) * sum_c conj(csm_c) * img_c
// ---------------------------------------------------------------------------
__global__ void __launch_bounds__(256) combine_kernel(
    const float* __restrict__ csr, const float* __restrict__ csi,
    float* __restrict__ out)
{
    int pix = blockIdx.x * blockDim.x + threadIdx.x;   // 0 .. N*N-1
    int ny = pix >> 9;
    int nx = pix & (NN - 1);

    float ar = 0.f, ai = 0.f;
#pragma unroll
    for (int c = 0; c < NC; c++) {
        float2 g = g_bufA[c * NN * NN + pix];
        float cr = csr[c * NN * NN + pix];
        float ci = csi[c * NN * NN + pix];
        // conj(csm) * img = (cr - i ci)(gr + i gi)
        ar += cr * g.x + ci * g.y;
        ai += cr * g.y - ci * g.x;
    }
    float sgn = ((ny + nx) & 1) ? -1.f : 1.f;
    out[pix]           = ar * sgn;
    out[NN * NN + pix] = ai * sgn;
}

// ---------------------------------------------------------------------------
extern "C" void kernel_launch(void* const* d_in, const int* in_sizes, int n_in,
                              void* d_out, int out_size)
{
    const float* xr   = (const float*)d_in[0];
    const float* xi   = (const float*)d_in[1];
    const float* csr  = (const float*)d_in[2];
    const float* csi  = (const float*)d_in[3];
    const float* traj = (const float*)d_in[4];
    const float* dcf  = (const float*)d_in[5];
    float* out = (float*)d_out;

    // zero gridA: NC*NN*NN float2 = 2,097,152 float4
    zero_kernel<<<8192, 256>>>();
    // scatter: NK*NC threads
    scatter_kernel<<<(NK * NC) / 256, 256>>>(xr, xi, traj, dcf);
    // row FFTs then column FFTs
    fft_kernel<false><<<dim3(NN / 4, NC), 256>>>();
    fft_kernel<true ><<<dim3(NN / 4, NC), 256>>>();
    // coil combine
    combine_kernel<<<(NN * NN) / 256, 256>>>(csr, csi, out);
}

// round 2
// speedup vs baseline: 1.3649x; 1.3649x over previous
#include <cuda_runtime.h>

#define NN 512
#define NC 16
#define NK 262144   // 2^18
#define LSTRIDE 578 // per-line smem stride (float2), padded for bank-conflict-free exchange

// Scratch grids: C x N x N complex, ping-pong between FFT passes. 32 MB each.
__device__ __align__(16) float2 g_bufA[NC * NN * NN];
__device__ __align__(16) float2 g_bufB[NC * NN * NN];

// ---------------------------------------------------------------------------
// complex helpers
// ---------------------------------------------------------------------------
__device__ __forceinline__ float2 cmul(float2 a, float2 b) {
    return make_float2(fmaf(a.x, b.x, -a.y * b.y), fmaf(a.x, b.y, a.y * b.x));
}
__device__ __forceinline__ float2 cadd(float2 a, float2 b) { return make_float2(a.x + b.x, a.y + b.y); }
__device__ __forceinline__ float2 csub(float2 a, float2 b) { return make_float2(a.x - b.x, a.y - b.y); }
__device__ __forceinline__ float2 muli(float2 a) { return make_float2(-a.y, a.x); }  // * (+i)

// 8-point unnormalized inverse DFT (sign +i), in place.
// y_j = sum_r x_r exp(+2*pi*i*j*r/8)
__device__ __forceinline__ void dft8(float2* x) {
    const float C = 0.70710678118654752440f;
    // stage 1 (radix-2, stride 4), twiddles W8^t
    float2 u0 = cadd(x[0], x[4]);
    float2 u1 = csub(x[0], x[4]);
    float2 u2 = cadd(x[1], x[5]);
    float2 d1 = csub(x[1], x[5]);
    float2 u3 = make_float2(C * (d1.x - d1.y), C * (d1.x + d1.y));    // d1 * ( C + iC)
    float2 u4 = cadd(x[2], x[6]);
    float2 u5 = muli(csub(x[2], x[6]));                               // * i
    float2 u6 = cadd(x[3], x[7]);
    float2 d3 = csub(x[3], x[7]);
    float2 u7 = make_float2(-C * (d3.x + d3.y), C * (d3.x - d3.y));   // d3 * (-C + iC)
    // stage 2
    float2 v0 = cadd(u0, u4);
    float2 v2 = csub(u0, u4);
    float2 v1 = cadd(u1, u5);
    float2 v3 = csub(u1, u5);
    float2 v4 = cadd(u2, u6);
    float2 v6 = muli(csub(u2, u6));
    float2 v5 = cadd(u3, u7);
    float2 v7 = muli(csub(u3, u7));
    // stage 3
    x[0] = cadd(v0, v4);
    x[4] = csub(v0, v4);
    x[1] = cadd(v1, v5);
    x[5] = csub(v1, v5);
    x[2] = cadd(v2, v6);
    x[6] = csub(v2, v6);
    x[3] = cadd(v3, v7);
    x[7] = csub(v3, v7);
}

// apply y_j *= exp(+i*ang)^j for j=1..7 via chained multiplies
__device__ __forceinline__ void twiddle7(float2* x, float ang) {
    float2 w;
    __sincosf(ang, &w.y, &w.x);
    float2 cw = w;
    x[1] = cmul(x[1], cw);
#pragma unroll
    for (int j = 2; j < 8; j++) { cw = cmul(cw, w); x[j] = cmul(x[j], cw); }
}

// ---------------------------------------------------------------------------
// Kernel 1: zero gridA (re-zeroed every graph replay)
// ---------------------------------------------------------------------------
__global__ void __launch_bounds__(256) zero_kernel() {
    int i = blockIdx.x * blockDim.x + threadIdx.x;
    float4* p = reinterpret_cast<float4*>(g_bufA);
    p[i] = make_float4(0.f, 0.f, 0.f, 0.f);
}

// ---------------------------------------------------------------------------
// Kernel 2: scatter-add. One thread per sample k, loops the 16 coils.
// ifftshift folded in as (-1)^(iy+ix) on the weight.
// ---------------------------------------------------------------------------
__global__ void __launch_bounds__(256) scatter_kernel(
    const float* __restrict__ xr, const float* __restrict__ xi,
    const float2* __restrict__ traj, const float* __restrict__ dcf)
{
    int k = blockIdx.x * blockDim.x + threadIdx.x;   // 0 .. NK-1
    float2 t = traj[k];
    int iy = __float2int_rn((t.x + 0.5f) * (float)NN) & (NN - 1);
    int ix = __float2int_rn((t.y + 0.5f) * (float)NN) & (NN - 1);
    float w = dcf[k];
    if ((iy + ix) & 1) w = -w;
    int cell = iy * NN + ix;
#pragma unroll
    for (int c = 0; c < NC; c++) {
        float vr = xr[c * NK + k] * w;
        float vi = xi[c * NK + k] * w;
        float* p = reinterpret_cast<float*>(&g_bufA[c * NN * NN + cell]);
        atomicAdd(p,     vr);
        atomicAdd(p + 1, vi);
    }
}

// ---------------------------------------------------------------------------
// Kernels 3/4: 512-point radix-8^3 Stockham inverse FFT, register-resident.
// 64 threads per line, 8 complex elements per thread, 2 smem exchanges.
// Stage s: q=t%s, p=t/s; in a_r=d[q+s*p+64r]; y=DFT8(a); y_j*=exp(2pi i j p s/512);
// out[q+8sp+sj]=y_j. Stages s=1,8,64. s=1 input and s=64 output are the
// natural stride-64 layout -> direct global I/O.
// COL=false: FFT along x, gridA->gridB, line=row  (fully coalesced)
// COL=true : FFT along y, gridB->gridA, line=col; role mapping line=tid&7
//            gives 64B-contiguous global chunks.
// ---------------------------------------------------------------------------
template<int LINES, bool COL>
__global__ void __launch_bounds__(LINES * 64) fft8_kernel() {
    __shared__ float2 sh[LINES * LSTRIDE];

    const int tid  = threadIdx.x;
    const int coil = blockIdx.y;
    const int l0   = blockIdx.x * LINES;

    int line, t;
    if (COL) { line = tid & (LINES - 1); t = tid / LINES; }
    else     { line = tid / 64;          t = tid & 63;    }

    const float2* __restrict__ src = (COL ? g_bufB : g_bufA) + coil * NN * NN;
    float2*       __restrict__ dst = (COL ? g_bufA : g_bufB) + coil * NN * NN;
    float2* ls = sh + line * LSTRIDE;

    float2 x[8];

    // load: element e = t + 64r
#pragma unroll
    for (int r = 0; r < 8; r++) {
        int e = t + 64 * r;
        x[r] = COL ? src[e * NN + l0 + line] : src[(l0 + line) * NN + e];
    }

    // ---- stage s=1: q=0, p=t ----
    dft8(x);
    twiddle7(x, 6.283185307179586f * (float)t * (1.0f / 512.0f));
#pragma unroll
    for (int j = 0; j < 8; j++) { int i = 8 * t + j; ls[i + (i >> 3)] = x[j]; }
    __syncthreads();

    // ---- stage s=8: q=t&7, p=t>>3 ----
    {
        const int q = t & 7, p = t >> 3;
#pragma unroll
        for (int r = 0; r < 8; r++) { int i = q + 8 * p + 64 * r; x[r] = ls[i + (i >> 3)]; }
        __syncthreads();
        dft8(x);
        twiddle7(x, 6.283185307179586f * (float)p * (1.0f / 64.0f));
#pragma unroll
        for (int j = 0; j < 8; j++) { int i = q + 64 * p + 8 * j; ls[i + (i >> 3)] = x[j]; }
    }
    __syncthreads();

    // ---- stage s=64: q=t, p=0 (no twiddle), output natural order ----
#pragma unroll
    for (int r = 0; r < 8; r++) { int i = t + 64 * r; x[r] = ls[i + (i >> 3)]; }
    dft8(x);

#pragma unroll
    for (int j = 0; j < 8; j++) {
        int e = t + 64 * j;
        if (COL) dst[e * NN + l0 + line] = x[j];
        else     dst[(l0 + line) * NN + e] = x[j];
    }
}

// ---------------------------------------------------------------------------
// Kernel 5: out = (-1)^(ny+nx) * sum_c conj(csm_c) * img_c
// ---------------------------------------------------------------------------
__global__ void __launch_bounds__(256) combine_kernel(
    const float* __restrict__ csr, const float* __restrict__ csi,
    float* __restrict__ out)
{
    int pix = blockIdx.x * blockDim.x + threadIdx.x;
    int ny = pix >> 9;
    int nx = pix & (NN - 1);

    float ar = 0.f, ai = 0.f;
#pragma unroll
    for (int c = 0; c < NC; c++) {
        float2 g = g_bufA[c * NN * NN + pix];
        float cr = csr[c * NN * NN + pix];
        float ci = csi[c * NN * NN + pix];
        ar = fmaf(cr, g.x, fmaf( ci, g.y, ar));
        ai = fmaf(cr, g.y, fmaf(-ci, g.x, ai));
    }
    float sgn = ((ny + nx) & 1) ? -1.f : 1.f;
    out[pix]           = ar * sgn;
    out[NN * NN + pix] = ai * sgn;
}

// ---------------------------------------------------------------------------
extern "C" void kernel_launch(void* const* d_in, const int* in_sizes, int n_in,
                              void* d_out, int out_size)
{
    const float* xr   = (const float*)d_in[0];
    const float* xi   = (const float*)d_in[1];
    const float* csr  = (const float*)d_in[2];
    const float* csi  = (const float*)d_in[3];
    const float* traj = (const float*)d_in[4];
    const float* dcf  = (const float*)d_in[5];
    float* out = (float*)d_out;

    zero_kernel<<<8192, 256>>>();
    scatter_kernel<<<NK / 256, 256>>>(xr, xi, (const float2*)traj, dcf);
    fft8_kernel<4, false><<<dim3(NN / 4, NC), 256>>>();   // rows:  A -> B
    fft8_kernel<8, true ><<<dim3(NN / 8, NC), 512>>>();   // cols:  B -> A
    combine_kernel<<<(NN * NN) / 256, 256>>>(csr, csi, out);
}

// round 3
// speedup vs baseline: 1.6619x; 1.2176x over previous
#include <cuda_runtime.h>

#define NN 512
#define NC 16
#define NK 262144   // 2^18
#define LSTRIDE 578 // per-line smem stride (float2), padded for conflict-free exchange

// Scratch grids. gridA: scatter target / row-FFT input. gridB: row-FFT output.
__device__ __align__(16) float2 g_bufA[NC * NN * NN];
__device__ __align__(16) float2 g_bufB[NC * NN * NN];

// ---------------------------------------------------------------------------
// complex helpers
// ---------------------------------------------------------------------------
__device__ __forceinline__ float2 cmul(float2 a, float2 b) {
    return make_float2(fmaf(a.x, b.x, -a.y * b.y), fmaf(a.x, b.y, a.y * b.x));
}
__device__ __forceinline__ float2 cadd(float2 a, float2 b) { return make_float2(a.x + b.x, a.y + b.y); }
__device__ __forceinline__ float2 csub(float2 a, float2 b) { return make_float2(a.x - b.x, a.y - b.y); }
__device__ __forceinline__ float2 muli(float2 a) { return make_float2(-a.y, a.x); }  // * (+i)

// 8-point unnormalized inverse DFT (sign +i), in place.
__device__ __forceinline__ void dft8(float2* x) {
    const float C = 0.70710678118654752440f;
    float2 u0 = cadd(x[0], x[4]);
    float2 u1 = csub(x[0], x[4]);
    float2 u2 = cadd(x[1], x[5]);
    float2 d1 = csub(x[1], x[5]);
    float2 u3 = make_float2(C * (d1.x - d1.y), C * (d1.x + d1.y));
    float2 u4 = cadd(x[2], x[6]);
    float2 u5 = muli(csub(x[2], x[6]));
    float2 u6 = cadd(x[3], x[7]);
    float2 d3 = csub(x[3], x[7]);
    float2 u7 = make_float2(-C * (d3.x + d3.y), C * (d3.x - d3.y));
    float2 v0 = cadd(u0, u4);
    float2 v2 = csub(u0, u4);
    float2 v1 = cadd(u1, u5);
    float2 v3 = csub(u1, u5);
    float2 v4 = cadd(u2, u6);
    float2 v6 = muli(csub(u2, u6));
    float2 v5 = cadd(u3, u7);
    float2 v7 = muli(csub(u3, u7));
    x[0] = cadd(v0, v4);
    x[4] = csub(v0, v4);
    x[1] = cadd(v1, v5);
    x[5] = csub(v1, v5);
    x[2] = cadd(v2, v6);
    x[6] = csub(v2, v6);
    x[3] = cadd(v3, v7);
    x[7] = csub(v3, v7);
}

__device__ __forceinline__ void twiddle7(float2* x, float ang) {
    float2 w;
    __sincosf(ang, &w.y, &w.x);
    float2 cw = w;
    x[1] = cmul(x[1], cw);
#pragma unroll
    for (int j = 2; j < 8; j++) { cw = cmul(cw, w); x[j] = cmul(x[j], cw); }
}

// 512-point FFT core on one line held in smem `ls` (padded i+(i>>3) layout):
// x[] arrives as natural-order stride-64 input; leaves as natural-order output.
__device__ __forceinline__ void fft512_core(float2* x, float2* ls, int t) {
    // stage s=1
    dft8(x);
    twiddle7(x, 6.283185307179586f * (float)t * (1.0f / 512.0f));
#pragma unroll
    for (int j = 0; j < 8; j++) { int i = 8 * t + j; ls[i + (i >> 3)] = x[j]; }
    __syncthreads();
    // stage s=8
    {
        const int q = t & 7, p = t >> 3;
#pragma unroll
        for (int r = 0; r < 8; r++) { int i = q + 8 * p + 64 * r; x[r] = ls[i + (i >> 3)]; }
        __syncthreads();
        dft8(x);
        twiddle7(x, 6.283185307179586f * (float)p * (1.0f / 64.0f));
#pragma unroll
        for (int j = 0; j < 8; j++) { int i = q + 64 * p + 8 * j; ls[i + (i >> 3)] = x[j]; }
    }
    __syncthreads();
    // stage s=64 (no twiddle)
#pragma unroll
    for (int r = 0; r < 8; r++) { int i = t + 64 * r; x[r] = ls[i + (i >> 3)]; }
    dft8(x);
}

// ---------------------------------------------------------------------------
// Kernel 1: zero gridA and out (both accumulated via atomics each replay)
// ---------------------------------------------------------------------------
#define GRID_F4 (NC * NN * NN / 2)   // gridA as float4 count: 2,097,152
#define OUT_F4  (2 * NN * NN / 4)    // out   as float4 count:   131,072

__global__ void __launch_bounds__(256) zero_kernel(float4* __restrict__ outv) {
    int i = blockIdx.x * blockDim.x + threadIdx.x;
    float4 z = make_float4(0.f, 0.f, 0.f, 0.f);
    if (i < GRID_F4) reinterpret_cast<float4*>(g_bufA)[i] = z;
    else             outv[i - GRID_F4] = z;
}

// ---------------------------------------------------------------------------
// Kernel 2: scatter-add, one thread per sample, 16 coils, float2 vector atomics.
// ifftshift folded in as (-1)^(iy+ix) on the weight.
// ---------------------------------------------------------------------------
__global__ void __launch_bounds__(256) scatter_kernel(
    const float* __restrict__ xr, const float* __restrict__ xi,
    const float2* __restrict__ traj, const float* __restrict__ dcf)
{
    int k = blockIdx.x * blockDim.x + threadIdx.x;
    float2 t = traj[k];
    int iy = __float2int_rn((t.x + 0.5f) * (float)NN) & (NN - 1);
    int ix = __float2int_rn((t.y + 0.5f) * (float)NN) & (NN - 1);
    float w = dcf[k];
    if ((iy + ix) & 1) w = -w;
    int cell = iy * NN + ix;
#pragma unroll
    for (int c = 0; c < NC; c++) {
        float2 v = make_float2(xr[c * NK + k] * w, xi[c * NK + k] * w);
        atomicAdd(&g_bufA[c * NN * NN + cell], v);
    }
}

// ---------------------------------------------------------------------------
// Kernel 3: row FFTs, gridA -> gridB. 4 lines/block, 256 threads.
// ---------------------------------------------------------------------------
__global__ void __launch_bounds__(256) fft_row_kernel() {
    __shared__ float2 sh[4 * LSTRIDE];
    const int tid  = threadIdx.x;
    const int coil = blockIdx.y;
    const int row  = blockIdx.x * 4 + tid / 64;
    const int t    = tid & 63;

    const float2* __restrict__ src = g_bufA + coil * NN * NN + row * NN;
    float2*       __restrict__ dst = g_bufB + coil * NN * NN + row * NN;
    float2* ls = sh + (tid / 64) * LSTRIDE;

    float2 x[8];
#pragma unroll
    for (int r = 0; r < 8; r++) x[r] = src[t + 64 * r];
    fft512_core(x, ls, t);
#pragma unroll
    for (int j = 0; j < 8; j++) dst[t + 64 * j] = x[j];
}

// ---------------------------------------------------------------------------
// Kernel 4: fused column FFTs + coil combine.
// Block = 8 columns x 4 coils (blockIdx.x: column group, blockIdx.y: coil group).
// Accumulates conj(csm)*img in registers across its 4 coils, then atomicAdds
// the signed partial into out. fftshift folded in as (-1)^(ny+nx).
// ---------------------------------------------------------------------------
__global__ void __launch_bounds__(512) fft_col_combine_kernel(
    const float* __restrict__ csr, const float* __restrict__ csi,
    float* __restrict__ out)
{
    __shared__ float2 sh[8 * LSTRIDE];
    const int tid  = threadIdx.x;
    const int l0   = blockIdx.x * 8;
    const int c0   = blockIdx.y * 4;
    const int line = tid & 7;           // column within group (fast -> coalesced)
    const int t    = tid >> 3;          // butterfly lane 0..63
    const int col  = l0 + line;

    float2* ls = sh + line * LSTRIDE;
    float2 acc[8];
#pragma unroll
    for (int j = 0; j < 8; j++) acc[j] = make_float2(0.f, 0.f);

    for (int cc = 0; cc < 4; cc++) {
        const int c = c0 + cc;
        const float2* __restrict__ src = g_bufB + c * NN * NN;
        const float*  __restrict__ cr  = csr + c * NN * NN;
        const float*  __restrict__ ci  = csi + c * NN * NN;

        float2 x[8];
#pragma unroll
        for (int r = 0; r < 8; r++) x[r] = src[(t + 64 * r) * NN + col];

        fft512_core(x, ls, t);

#pragma unroll
        for (int j = 0; j < 8; j++) {
            int pix = (t + 64 * j) * NN + col;
            float a = cr[pix], b = ci[pix];
            // conj(csm) * img
            acc[j].x = fmaf(a, x[j].x, fmaf( b, x[j].y, acc[j].x));
            acc[j].y = fmaf(a, x[j].y, fmaf(-b, x[j].x, acc[j].y));
        }
        __syncthreads();   // protect smem before next coil's stage-1 store
    }

#pragma unroll
    for (int j = 0; j < 8; j++) {
        int ny  = t + 64 * j;
        int pix = ny * NN + col;
        float sgn = ((ny + col) & 1) ? -1.f : 1.f;
        atomicAdd(&out[pix],           sgn * acc[j].x);
        atomicAdd(&out[NN * NN + pix], sgn * acc[j].y);
    }
}

// ---------------------------------------------------------------------------
extern "C" void kernel_launch(void* const* d_in, const int* in_sizes, int n_in,
                              void* d_out, int out_size)
{
    const float* xr   = (const float*)d_in[0];
    const float* xi   = (const float*)d_in[1];
    const float* csr  = (const float*)d_in[2];
    const float* csi  = (const float*)d_in[3];
    const float* traj = (const float*)d_in[4];
    const float* dcf  = (const float*)d_in[5];
    float* out = (float*)d_out;

    zero_kernel<<<(GRID_F4 + OUT_F4) / 256, 256>>>((float4*)out);
    scatter_kernel<<<NK / 256, 256>>>(xr, xi, (const float2*)traj, dcf);
    fft_row_kernel<<<dim3(NN / 4, NC), 256>>>();
    fft_col_combine_kernel<<<dim3(NN / 8, NC / 4), 512>>>(csr, csi, out);
}